// round 4
// baseline (speedup 1.0000x reference)
#include <cuda_runtime.h>
#include <math.h>

#define NCODES 4096
#define CDIM   256
#define NTOK   32768
#define NC_OUT (NTOK * CDIM)   /* 8388608 */

#define TM 64
#define TN 128
#define KC 64
#define AS_STRIDE 260   /* multiple of 4 (float4 aligned), 4*260 % 32 != 0 */
#define BS_STRIDE 65    /* odd: 16 lanes * stride -> 16 distinct banks     */
#define SMEM_BYTES ((TM * AS_STRIDE + TN * BS_STRIDE + TN) * 4)

__device__ float g_enorm[NCODES];
__device__ int   g_counts[NCODES];
__device__ float g_loss;
__device__ int   g_valid;
__device__ int   g_idx[NTOK];

/* ------------------------------------------------------------------ */
__global__ void zero_kernel() {
    int i = blockIdx.x * 256 + threadIdx.x;
    if (i < NCODES) g_counts[i] = 0;
    if (i == 0) { g_loss = 0.0f; g_valid = 0; }
}

/* ------------------------------------------------------------------ */
__global__ void enorm_kernel(const float* __restrict__ e) {
    int warp = (blockIdx.x * blockDim.x + threadIdx.x) >> 5;
    int lane = threadIdx.x & 31;
    if (warp >= NCODES) return;
    const float* row = e + (size_t)warp * CDIM;
    float s = 0.0f;
#pragma unroll
    for (int i = 0; i < CDIM / 32; i++) {
        float v = row[lane + 32 * i];
        s += v * v;
    }
#pragma unroll
    for (int o = 16; o; o >>= 1) s += __shfl_down_sync(0xffffffffu, s, o);
    if (lane == 0) g_enorm[warp] = s;
}

/* ------------------------------------------------------------------ */
/* Fused distance-GEMM + argmin. Block: 64 tokens x all 4096 codes.    */
/* Distances computed EXACTLY as the reference does:                   */
/*   d = fl( fl( Z - 2*dot ) + e_norm ),  Z = ||z||^2 (fp32)           */
/* (2*dot is exact, so FMA(-2,dot,Z) == fl(Z - fl(2*dot)) bit-exact).  */
__global__ __launch_bounds__(256, 2)
void argmin_kernel(const float* __restrict__ z, const float* __restrict__ e,
                   float* __restrict__ out_idx_f) {
    extern __shared__ float sm[];
    float* As = sm;                       /* [TM][AS_STRIDE] full K      */
    float* Bs = As + TM * AS_STRIDE;      /* [TN][BS_STRIDE] one K-chunk */
    float* Es = Bs + TN * BS_STRIDE;      /* [TN] code norms             */

    const int tid = threadIdx.x;
    const int tx  = tid & 15;             /* code group  */
    const int ty  = tid >> 4;             /* token group */
    const int t0  = blockIdx.x * TM;

    /* Load A tile (64 tokens x 256 dims), coalesced float4, full K resident */
    {
        const float4* zg = (const float4*)(z + (size_t)t0 * CDIM);
#pragma unroll
        for (int i = 0; i < 16; i++) {
            int v  = tid + i * 256;
            int m  = v >> 6;              /* 64 float4 per token row */
            int k4 = v & 63;
            float4 val = zg[(size_t)m * (CDIM / 4) + k4];
            *(float4*)(As + m * AS_STRIDE + k4 * 4) = val;
        }
    }
    __syncthreads();

    /* Per-token squared norm Z (fp32; summation order is argmin-neutral
       because ulp-multiple shifts preserve the quantized ordering). */
    float Zi[4];
#pragma unroll
    for (int i = 0; i < 4; i++) {
        const float* row = As + (ty + 16 * i) * AS_STRIDE;
        float s = 0.0f;
#pragma unroll 8
        for (int k = 0; k < CDIM; k++) s = fmaf(row[k], row[k], s);
        Zi[i] = s;
    }

    float best[4];
    int   bidx[4];
#pragma unroll
    for (int i = 0; i < 4; i++) { best[i] = 3.4e38f; bidx[i] = 0; }

    for (int jt = 0; jt < NCODES; jt += TN) {
        if (tid < TN) Es[tid] = g_enorm[jt + tid];

        float acc[4][8];
#pragma unroll
        for (int i = 0; i < 4; i++)
#pragma unroll
            for (int j = 0; j < 8; j++) acc[i][j] = 0.0f;

        for (int kc = 0; kc < CDIM; kc += KC) {
            __syncthreads();
            /* Load B chunk: 128 codes x 64 dims (coalesced float4 from gmem) */
#pragma unroll
            for (int i = 0; i < 8; i++) {
                int v  = tid + i * 256;
                int n  = v >> 4;          /* 16 float4 per code-row chunk */
                int k4 = v & 15;
                float4 val = *(const float4*)(e + (size_t)(jt + n) * CDIM + kc + k4 * 4);
                float* dst = Bs + n * BS_STRIDE + k4 * 4;
                dst[0] = val.x; dst[1] = val.y; dst[2] = val.z; dst[3] = val.w;
            }
            __syncthreads();

#pragma unroll 16
            for (int kk = 0; kk < KC; kk++) {
                float a[4], b[8];
#pragma unroll
                for (int i = 0; i < 4; i++)
                    a[i] = As[(ty + 16 * i) * AS_STRIDE + kc + kk];
#pragma unroll
                for (int j = 0; j < 8; j++)
                    b[j] = Bs[(tx + 16 * j) * BS_STRIDE + kk];
#pragma unroll
                for (int i = 0; i < 4; i++)
#pragma unroll
                    for (int j = 0; j < 8; j++)
                        acc[i][j] = fmaf(a[i], b[j], acc[i][j]);
            }
        }

        /* Reference-exact distance: (Z - 2*dot) + e_norm, two roundings */
#pragma unroll
        for (int i = 0; i < 4; i++) {
#pragma unroll
            for (int j = 0; j < 8; j++) {
                int   n = jt + tx + 16 * j;
                float t = __fmaf_rn(-2.0f, acc[i][j], Zi[i]);
                float d = __fadd_rn(t, Es[tx + 16 * j]);
                if (d < best[i] || (d == best[i] && n < bidx[i])) {
                    best[i] = d; bidx[i] = n;
                }
            }
        }
        __syncthreads();   /* protect Es/Bs before next tile rewrites them */
    }

    /* Cross-thread reduction: 16 lanes (same ty) share 4 tokens each */
#pragma unroll
    for (int i = 0; i < 4; i++) {
        float d = best[i];
        int   n = bidx[i];
#pragma unroll
        for (int o = 8; o; o >>= 1) {
            float od = __shfl_down_sync(0xffffffffu, d, o, 16);
            int   on = __shfl_down_sync(0xffffffffu, n, o, 16);
            if (od < d || (od == d && on < n)) { d = od; n = on; }
        }
        if (tx == 0) {
            int m = ty + 16 * i;
            g_idx[t0 + m]     = n;
            out_idx_f[t0 + m] = (float)n;
        }
    }
}

/* ------------------------------------------------------------------ */
/* Gather z_q / z_q_st, accumulate loss, valid count, code histogram.  */
__global__ void gather_kernel(const float* __restrict__ z,
                              const int* __restrict__ mask,
                              const float* __restrict__ e,
                              float* __restrict__ out) {
    __shared__ float s_loss[8];
    __shared__ int   s_valid[8];
    int wid  = threadIdx.x >> 5;
    int lane = threadIdx.x & 31;
    int t    = blockIdx.x * 8 + wid;

    int mk  = mask[t];
    int idx = g_idx[t];
    const float4* zr = (const float4*)(z + (size_t)t * CDIM);
    const float4* er = (const float4*)(e + (size_t)idx * CDIM);
    float4* o1 = (float4*)(out + (size_t)t * CDIM);
    float4* o2 = (float4*)(out + (size_t)NC_OUT + (size_t)t * CDIM);

    float ls = 0.0f;
#pragma unroll
    for (int i = 0; i < 2; i++) {
        int c = lane + 32 * i;
        float4 ev = er[c];
        float4 zv = zr[c];
        float4 q;
        if (mk) {
            q = ev;
            float dx = ev.x - zv.x, dy = ev.y - zv.y;
            float dz = ev.z - zv.z, dw = ev.w - zv.w;
            ls += dx * dx + dy * dy + dz * dz + dw * dw;
        } else {
            q = make_float4(0.0f, 0.0f, 0.0f, 0.0f);
        }
        o1[c] = q;
        o2[c] = q;
    }
#pragma unroll
    for (int o = 16; o; o >>= 1) ls += __shfl_down_sync(0xffffffffu, ls, o);
    if (lane == 0) {
        s_loss[wid]  = ls;
        s_valid[wid] = mk;
        if (mk) atomicAdd(&g_counts[idx], 1);
    }
    __syncthreads();
    if (threadIdx.x == 0) {
        float tot = 0.0f; int v = 0;
#pragma unroll
        for (int w = 0; w < 8; w++) { tot += s_loss[w]; v += s_valid[w]; }
        atomicAdd(&g_loss, tot);
        atomicAdd(&g_valid, v);
    }
}

/* ------------------------------------------------------------------ */
__global__ void finalize_kernel(float* __restrict__ out) {
    __shared__ float red[256];
    int tid = threadIdx.x;
    float nv    = (float)g_valid;
    float denom = nv + 1e-8f;
    float ent = 0.0f;
    for (int i = tid; i < NCODES; i += 256) {
        float p = (float)g_counts[i] / denom;
        ent += p * logf(p + 1e-8f);
    }
    red[tid] = ent;
    __syncthreads();
    for (int s = 128; s; s >>= 1) {
        if (tid < s) red[tid] += red[tid + s];
        __syncthreads();
    }
    if (tid == 0) {
        float valid = fmaxf(nv, 1.0f);
        float loss  = g_loss / valid;
        float* o = out + 2 * (size_t)NC_OUT + NTOK;
        o[0] = loss * 1.25f;   /* vq_loss = codebook + BETA*commitment */
        o[1] = loss;           /* codebook_loss   */
        o[2] = loss;           /* commitment_loss */
        o[3] = expf(-red[0]);  /* perplexity      */
    }
}

/* ------------------------------------------------------------------ */
extern "C" void kernel_launch(void* const* d_in, const int* in_sizes, int n_in,
                              void* d_out, int out_size) {
    const float* z    = (const float*)d_in[0];
    const int*   mask = (const int*)d_in[1];
    const float* e    = (const float*)d_in[2];
    float*       out  = (float*)d_out;

    cudaFuncSetAttribute(argmin_kernel,
                         cudaFuncAttributeMaxDynamicSharedMemorySize, SMEM_BYTES);

    zero_kernel<<<(NCODES + 255) / 256, 256>>>();
    enorm_kernel<<<NCODES / 8, 256>>>(e);
    argmin_kernel<<<NTOK / TM, 256, SMEM_BYTES>>>(z, e, out + 2 * (size_t)NC_OUT);
    gather_kernel<<<NTOK / 8, 256>>>(z, mask, e, out);
    finalize_kernel<<<1, 256>>>(out);
}